// round 16
// baseline (speedup 1.0000x reference)
#include <cuda_runtime.h>
#include <cuda_fp16.h>
#include <stdint.h>

#define N_MAX 50000
#define E_MAX 1600000
#define IN_CH 128
#define HID 64
#define OUT 64
#define XS 68        // smem row stride (floats) for 64-wide activation tiles
#define SCAN_B 256   // scan chunk
#define DEG_B 1024   // degree-count blocks fused into k_main

// ---- scratch (device globals: no allocation allowed) ----
__device__ __align__(16) __half g_h2s [N_MAX * HID];  // fp16(relu(x@W1+b1)@Wg), UNSCALED
__device__ __align__(16) float  g_acc [N_MAX * HID];  // aggregated messages (fp32)
__device__ int   g_degc  [N_MAX];                     // edge in-degree (no self loop)
__device__ int   g_start [N_MAX];                     // CSR offsets (exclusive scan)
__device__ int   g_cursor[N_MAX];
__device__ int   g_srcid [E_MAX];                     // CSR: source node per slot
__device__ int   g_bsum  [SCAN_B];                    // scan block sums
__device__ float g_dinv  [N_MAX];                     // rsqrt(deg+1), filled by k_scan3
__device__ float g_b2p[OUT];                          // bg@W2 + b2
__device__ int   g_is32;

// ---------------------------------------------------------------------------
// zero degc + dtype sniff (int32 read as int64 -> out-of-range values)
// ---------------------------------------------------------------------------
__global__ void k_init(const long long* __restrict__ ei, int n, int E) {
    int i = blockIdx.x * blockDim.x + threadIdx.x;
    if (i < n) g_degc[i] = 0;
    if (blockIdx.x == 0 && threadIdx.x == 0) {
        int bad = 0;
        for (int j = 0; j < 16; j++) {
            long long a = ei[j], b = ei[E + j];
            if (a < 0 || a >= (long long)n) bad = 1;
            if (b < 0 || b >= (long long)n) bad = 1;
        }
        g_is32 = bad;
    }
}

__global__ void k_init2(int n) {
    int i = blockIdx.x * blockDim.x + threadIdx.x;
    if (i < n) g_cursor[i] = 0;
}

__global__ void k_b2p(const float* __restrict__ bg, const float* __restrict__ W2,
                      const float* __restrict__ b2) {
    int c = threadIdx.x;
    if (c < OUT) {
        float s = b2[c];
        #pragma unroll
        for (int k = 0; k < HID; k++) s = fmaf(bg[k], W2[k * OUT + c], s);
        g_b2p[c] = s;
    }
}

// ---------------------------------------------------------------------------
// GEMM helpers: 8x4 register tile, float4 operand loads.
// A-loads are half-warp broadcasts (cheap); W LDS amortized over 8 rows.
// ---------------------------------------------------------------------------
__device__ __forceinline__ float f4c(float4 v, int k) {
    return (k == 0) ? v.x : (k == 1) ? v.y : (k == 2) ? v.z : v.w;
}

__device__ __forceinline__ void gemm64_84(float acc[8][4], const float* sA,
                                          const float* sW, int r0, int c0, int wid) {
    #pragma unroll 2
    for (int k = 0; k < 64; k += 4) {
        float4 a[8];
        #pragma unroll
        for (int i = 0; i < 8; i++)
            a[i] = *(const float4*)(sA + (r0 + i) * XS + k);
        #pragma unroll
        for (int kk = 0; kk < 4; kk++) {
            float4 w = *(const float4*)(sW + (k + kk) * wid + c0);
            #pragma unroll
            for (int i = 0; i < 8; i++) {
                float av = f4c(a[i], kk);
                acc[i][0] = fmaf(av, w.x, acc[i][0]);
                acc[i][1] = fmaf(av, w.y, acc[i][1]);
                acc[i][2] = fmaf(av, w.z, acc[i][2]);
                acc[i][3] = fmaf(av, w.w, acc[i][3]);
            }
        }
    }
}

// ---------------------------------------------------------------------------
// k_main: block-specialized.
//   blocks [0, DEG_B)        : degree count over col half of edge_index
//   blocks [DEG_B, DEG_B+GB) : fused lin1+Wg GEMM, 64x64 tile, 128 threads,
//                              8x4 register tile; h2s stored fp16 UNSCALED
//                              (dinv applied later in k_gather — g_degc is
//                              being written concurrently by deg blocks).
// ---------------------------------------------------------------------------
__global__ __launch_bounds__(128) void k_main(const float* __restrict__ x,
                                              const float* __restrict__ W1,
                                              const float* __restrict__ b1,
                                              const float* __restrict__ Wg,
                                              const void* __restrict__ ei_raw,
                                              int n, int E) {
    if (blockIdx.x < DEG_B) {
        for (int e = blockIdx.x * 128 + threadIdx.x; e < E; e += DEG_B * 128) {
            int c;
            if (g_is32) c = ((const int*)ei_raw)[E + e];
            else        c = (int)((const long long*)ei_raw)[E + e];
            atomicAdd(&g_degc[c], 1);
        }
        return;
    }

    __shared__ float sW[64 * HID];    // 16KB
    __shared__ float sX[64 * XS];     // 17.4KB
    const int tid = threadIdx.x;
    const int tx = tid & 15, ty = tid >> 4;     // 16 x 8
    const int n0 = (blockIdx.x - DEG_B) * 64;
    const int c0 = tx * 4, r0 = ty * 8;

    // ---- phase 1: acc = x @ W1 + b1  (K=128 in two 64-chunks)
    float4 bb = *(const float4*)(b1 + c0);
    float acc[8][4];
    #pragma unroll
    for (int i = 0; i < 8; i++) {
        acc[i][0] = bb.x; acc[i][1] = bb.y; acc[i][2] = bb.z; acc[i][3] = bb.w;
    }

    for (int kc = 0; kc < 2; kc++) {
        for (int i = tid; i < 64 * (HID / 4); i += 128)
            ((float4*)sW)[i] = ((const float4*)(W1 + kc * 64 * HID))[i];
        for (int i = tid; i < 64 * 16; i += 128) {
            int r = i >> 4, c4 = i & 15;
            int node = n0 + r;
            float4 v = (node < n)
                ? *(const float4*)(x + (size_t)node * IN_CH + kc * 64 + c4 * 4)
                : make_float4(0.f, 0.f, 0.f, 0.f);
            *(float4*)(sX + r * XS + c4 * 4) = v;
        }
        __syncthreads();
        gemm64_84(acc, sX, sW, r0, c0, HID);
        __syncthreads();
    }

    // ---- handoff: sX <- relu(acc), sW <- Wg
    #pragma unroll
    for (int i = 0; i < 8; i++) {
        float4 v = make_float4(fmaxf(acc[i][0], 0.f), fmaxf(acc[i][1], 0.f),
                               fmaxf(acc[i][2], 0.f), fmaxf(acc[i][3], 0.f));
        *(float4*)(sX + (r0 + i) * XS + c0) = v;
    }
    for (int i = tid; i < HID * HID / 4; i += 128)
        ((float4*)sW)[i] = ((const float4*)Wg)[i];
    __syncthreads();

    // ---- phase 2: h2 = h1 @ Wg, store fp16 (unscaled)
    #pragma unroll
    for (int i = 0; i < 8; i++)
        #pragma unroll
        for (int j = 0; j < 4; j++) acc[i][j] = 0.f;

    gemm64_84(acc, sX, sW, r0, c0, HID);

    #pragma unroll
    for (int i = 0; i < 8; i++) {
        int node = n0 + r0 + i;
        if (node >= n) continue;
        __half2 h01 = __floats2half2_rn(acc[i][0], acc[i][1]);
        __half2 h23 = __floats2half2_rn(acc[i][2], acc[i][3]);
        __half2* dst = (__half2*)(g_h2s + (size_t)node * HID + c0);
        dst[0] = h01;
        dst[1] = h23;
    }
}

// ---- 3-kernel exclusive prefix scan of g_degc into g_start -----------------
__global__ void k_scan1(int n) {
    __shared__ int s[SCAN_B];
    int t = threadIdx.x, i = blockIdx.x * SCAN_B + t;
    int v = (i < n) ? g_degc[i] : 0;
    s[t] = v; __syncthreads();
    for (int off = 1; off < SCAN_B; off <<= 1) {
        int add = (t >= off) ? s[t - off] : 0;
        __syncthreads();
        s[t] += add;
        __syncthreads();
    }
    if (i < n) g_start[i] = s[t] - v;          // exclusive within chunk
    if (t == SCAN_B - 1) g_bsum[blockIdx.x] = s[t];
}

__global__ void k_scan2(int nb) {
    __shared__ int s[SCAN_B];
    int t = threadIdx.x;
    int v = (t < nb) ? g_bsum[t] : 0;
    s[t] = v; __syncthreads();
    for (int off = 1; off < SCAN_B; off <<= 1) {
        int add = (t >= off) ? s[t - off] : 0;
        __syncthreads();
        s[t] += add;
        __syncthreads();
    }
    if (t < nb) g_bsum[t] = s[t] - v;          // exclusive block offsets
}

__global__ void k_scan3(int n) {
    int i = blockIdx.x * blockDim.x + threadIdx.x;
    if (i < n) {
        g_start[i] += g_bsum[i / SCAN_B];
        g_dinv[i] = rsqrtf((float)(g_degc[i] + 1));
    }
}

// ---- fill CSR: g_srcid[start[c] + cursor[c]++] = r -------------------------
__global__ void k_fill(const void* __restrict__ ei_raw, int E) {
    for (int e = blockIdx.x * blockDim.x + threadIdx.x; e < E;
         e += gridDim.x * blockDim.x) {
        int r, c;
        if (g_is32) {
            const int* ei = (const int*)ei_raw;
            r = ei[e]; c = ei[E + e];
        } else {
            const long long* ei = (const long long*)ei_raw;
            r = (int)ei[e]; c = (int)ei[E + e];
        }
        int pos = g_start[c] + atomicAdd(&g_cursor[c], 1);
        g_srcid[pos] = r;
    }
}

// ---------------------------------------------------------------------------
// CSR gather, 2 edges per warp-iteration, dinv[src] applied per edge:
//   lanes 0-15  handle edge j, lanes 16-31 edge j+1 (8B half4 per lane).
// shfl_down(16) merges halves; lanes 0-15 add dinv[node]*self, store float4.
// ---------------------------------------------------------------------------
__global__ __launch_bounds__(256) void k_gather(int n) {
    const int warp = (blockIdx.x * 256 + threadIdx.x) >> 5;
    const int lane = threadIdx.x & 31;
    if (warp >= n) return;
    const int node = warp;
    const int beg = g_start[node];
    const int cnt = g_degc[node];
    const int g = lane >> 4;        // edge slot within pair
    const int s = lane & 15;        // channel quad

    const uint2* __restrict__ src = (const uint2*)g_h2s;  // 8B = 4 half
    float4 a = make_float4(0.f, 0.f, 0.f, 0.f);

    int j = 0;
    for (; j + 4 <= cnt; j += 4) {                        // 2 pairs unrolled
        int r0 = __ldg(&g_srcid[beg + j + g]);
        int r1 = __ldg(&g_srcid[beg + j + 2 + g]);
        float d0 = __ldg(&g_dinv[r0]);
        float d1 = __ldg(&g_dinv[r1]);
        uint2 p0 = __ldg(&src[(size_t)r0 * 16 + s]);
        uint2 p1 = __ldg(&src[(size_t)r1 * 16 + s]);
        float2 f0 = __half22float2(*(__half2*)&p0.x);
        float2 f1 = __half22float2(*(__half2*)&p0.y);
        float2 f2 = __half22float2(*(__half2*)&p1.x);
        float2 f3 = __half22float2(*(__half2*)&p1.y);
        a.x = fmaf(d0, f0.x, fmaf(d1, f2.x, a.x));
        a.y = fmaf(d0, f0.y, fmaf(d1, f2.y, a.y));
        a.z = fmaf(d0, f1.x, fmaf(d1, f3.x, a.z));
        a.w = fmaf(d0, f1.y, fmaf(d1, f3.y, a.w));
    }
    for (; j + 2 <= cnt; j += 2) {                        // one pair
        int r = __ldg(&g_srcid[beg + j + g]);
        float d = __ldg(&g_dinv[r]);
        uint2 p = __ldg(&src[(size_t)r * 16 + s]);
        float2 f0 = __half22float2(*(__half2*)&p.x);
        float2 f1 = __half22float2(*(__half2*)&p.y);
        a.x = fmaf(d, f0.x, a.x); a.y = fmaf(d, f0.y, a.y);
        a.z = fmaf(d, f1.x, a.z); a.w = fmaf(d, f1.y, a.w);
    }
    if (j < cnt && g == 0) {                              // odd tail
        int r = __ldg(&g_srcid[beg + j]);
        float d = __ldg(&g_dinv[r]);
        uint2 p = __ldg(&src[(size_t)r * 16 + s]);
        float2 f0 = __half22float2(*(__half2*)&p.x);
        float2 f1 = __half22float2(*(__half2*)&p.y);
        a.x = fmaf(d, f0.x, a.x); a.y = fmaf(d, f0.y, a.y);
        a.z = fmaf(d, f1.x, a.z); a.w = fmaf(d, f1.y, a.w);
    }

    a.x += __shfl_down_sync(0xffffffffu, a.x, 16);
    a.y += __shfl_down_sync(0xffffffffu, a.y, 16);
    a.z += __shfl_down_sync(0xffffffffu, a.z, 16);
    a.w += __shfl_down_sync(0xffffffffu, a.w, 16);

    if (g == 0) {
        float d = __ldg(&g_dinv[node]);                   // self loop
        uint2 p = __ldg(&src[(size_t)node * 16 + s]);
        float2 f0 = __half22float2(*(__half2*)&p.x);
        float2 f1 = __half22float2(*(__half2*)&p.y);
        a.x = fmaf(d, f0.x, a.x); a.y = fmaf(d, f0.y, a.y);
        a.z = fmaf(d, f1.x, a.z); a.w = fmaf(d, f1.y, a.w);
        ((float4*)g_acc)[(size_t)node * 16 + s] = a;
    }
}

// ---------------------------------------------------------------------------
// out = (dinv * acc) @ W2 + b2'.  8x4 register tile, 128 threads.
// ---------------------------------------------------------------------------
__global__ __launch_bounds__(128) void k_out(const float* __restrict__ W2,
                                             float* __restrict__ out, int n) {
    __shared__ float sW[HID * OUT];
    __shared__ float sA[64 * XS];
    const int tid = threadIdx.x;
    const int tx = tid & 15, ty = tid >> 4;
    const int n0 = blockIdx.x * 64;
    const int c0 = tx * 4, r0 = ty * 8;

    for (int i = tid; i < HID * OUT / 4; i += 128)
        ((float4*)sW)[i] = ((const float4*)W2)[i];
    for (int i = tid; i < 64 * 16; i += 128) {
        int r = i >> 4, c4 = i & 15;
        int node = n0 + r;
        float4 v = make_float4(0.f, 0.f, 0.f, 0.f);
        if (node < n) {
            v = ((const float4*)(g_acc + (size_t)node * HID))[c4];
            float di = g_dinv[node];
            v.x *= di; v.y *= di; v.z *= di; v.w *= di;
        }
        *(float4*)(sA + r * XS + c4 * 4) = v;
    }
    __syncthreads();

    float4 bb = ((const float4*)g_b2p)[tx];
    float acc[8][4];
    #pragma unroll
    for (int i = 0; i < 8; i++) {
        acc[i][0] = bb.x; acc[i][1] = bb.y; acc[i][2] = bb.z; acc[i][3] = bb.w;
    }

    gemm64_84(acc, sA, sW, r0, c0, OUT);

    #pragma unroll
    for (int i = 0; i < 8; i++) {
        int node = n0 + r0 + i;
        if (node >= n) continue;
        float4 v = make_float4(acc[i][0], acc[i][1], acc[i][2], acc[i][3]);
        *(float4*)(out + (size_t)node * OUT + c0) = v;
    }
}

// ---------------------------------------------------------------------------
// Inputs (metadata order): x, edge_index, W1, b1, Wg, bg, W2, b2
// ---------------------------------------------------------------------------
extern "C" void kernel_launch(void* const* d_in, const int* in_sizes, int n_in,
                              void* d_out, int out_size) {
    const float* x  = (const float*)d_in[0];
    const void*  ei = d_in[1];
    const float* W1 = (const float*)d_in[2];
    const float* b1 = (const float*)d_in[3];
    const float* Wg = (const float*)d_in[4];
    const float* bg = (const float*)d_in[5];
    const float* W2 = (const float*)d_in[6];
    const float* b2 = (const float*)d_in[7];
    float* out = (float*)d_out;

    const int n = in_sizes[0] / IN_CH;   // 50000
    const int E = in_sizes[1] / 2;       // 1.6M
    const int nb = (n + SCAN_B - 1) / SCAN_B;
    const int gb = (n + 63) / 64;

    k_init<<<(n + 255) / 256, 256>>>((const long long*)ei, n, E);        // 1
    k_init2<<<(n + 255) / 256, 256>>>(n);                                // 2
    k_b2p<<<1, 64>>>(bg, W2, b2);                                        // 3
    k_main<<<DEG_B + gb, 128>>>(x, W1, b1, Wg, ei, n, E);                // 4 (profiled)
    k_scan1<<<nb, SCAN_B>>>(n);                                          // 5
    k_scan2<<<1, SCAN_B>>>(nb);                                          // 6
    k_scan3<<<nb, SCAN_B>>>(n);                                          // 7
    k_fill<<<2048, 256>>>(ei, E);                                        // 8
    k_gather<<<(n * 32 + 255) / 256, 256>>>(n);                          // 9
    k_out<<<gb, 128>>>(W2, out, n);                                      // 10
}